// round 3
// baseline (speedup 1.0000x reference)
#include <cuda_runtime.h>
#include <math.h>

#define IMAGE_W 256
#define IMAGE_H 256
#define EPS 1e-7f
#define SIGMA2 0.02f

#define B 16
#define N 64
#define C 3
#define PH 32
#define PW 32
#define TILE 32

// One block per (batch, 32x32 tile). 256 threads: thread (lx, g) owns pixel
// column x = tx0+lx, rows y = ty0 + 4g .. ty0 + 4g+3 (4 consecutive rows).
// Patch taps are read directly from global (L2-hot); no in-loop barriers.
__global__ void __launch_bounds__(256) brush_fused_kernel(
    const float* __restrict__ brushes,   // [B, N, 2]
    const float* __restrict__ patches,   // [B, N, 3, 32, 32]
    float* __restrict__ out)             // [B, 3, 256, 256]
{
    const int b    = blockIdx.y;
    const int tile = blockIdx.x;           // 0..63
    const int tx0  = (tile & 7) * TILE;
    const int ty0  = (tile >> 3) * TILE;
    const int tid  = threadIdx.x;

    __shared__ float  sbx[N], sby[N];
    __shared__ int    sfx[N], sfy[N];
    __shared__ float4 sw[N];   // (wx0, wx1, wy0/64, wy1/64)

    if (tid < N) {
        sbx[tid] = brushes[(b * N + tid) * 2 + 0];
        sby[tid] = brushes[(b * N + tid) * 2 + 1];
    }
    __syncthreads();

    if (tid < N) {
        float mnx = sbx[0], mxx = sbx[0], mny = sby[0], mxy = sby[0];
#pragma unroll
        for (int k = 1; k < N; k++) {
            mnx = fminf(mnx, sbx[k]); mxx = fmaxf(mxx, sbx[k]);
            mny = fminf(mny, sby[k]); mxy = fmaxf(mxy, sby[k]);
        }
        const float gx = (sbx[tid] - mnx) / (mxx - mnx + EPS) * (float)IMAGE_W;
        const float gy = (sby[tid] - mny) / (mxy - mny + EPS) * (float)IMAGE_H;

        const float axc = gx - 15.5f;          // ux(q) = gx + q - 15.5
        const float fx0f = floorf(axc);
        const float dx = axc - fx0f;
        const float ayc = gy - 15.4f;          // uy(p) = gy + p - 15.4
        const float fy0f = floorf(ayc);
        const float dy = ayc - fy0f;

        const float gx0 = __expf(-(dx * dx) / SIGMA2);
        const float gx1 = __expf(-((1.0f - dx) * (1.0f - dx)) / SIGMA2);
        const float wx0 = gx0 / (gx0 + gx1 + EPS);
        const float wx1 = gx1 / (gx0 + gx1 + EPS);

        const float gy0 = __expf(-(dy * dy) / SIGMA2);
        const float gy1 = __expf(-((1.0f - dy) * (1.0f - dy)) / SIGMA2);
        const float s  = 1.0f / 64.0f;         // fold the /N into wy
        const float wy0 = gy0 / (gy0 + gy1 + EPS) * s;
        const float wy1 = gy1 / (gy0 + gy1 + EPS) * s;

        sfx[tid] = (int)fx0f;
        sfy[tid] = (int)fy0f;
        sw[tid]  = make_float4(wx0, wx1, wy0, wy1);
    }
    __syncthreads();

    const int lx    = tid & 31;                // x within tile (= lane)
    const int g     = tid >> 5;                // row group 0..7
    const int x     = tx0 + lx;
    const int ybase = ty0 + g * 4;             // rows ybase..ybase+3

    float acc[4][C];
#pragma unroll
    for (int k = 0; k < 4; k++)
#pragma unroll
        for (int c = 0; c < C; c++) acc[k][c] = 0.0f;

    const float* Pb = patches + (size_t)(b * N) * (C * PH * PW);

    for (int n = 0; n < N; n++) {
        const int fx = sfx[n];
        const int fy = sfy[n];
        // window: cols [fx, fx+32], rows [fy, fy+32]; block-uniform reject
        if (fx > tx0 + 31 || fx + 32 < tx0 || fy > ty0 + 31 || fy + 32 < ty0)
            continue;

        const int i = x - fx;                  // window col for this thread
        if ((unsigned)i > 32u) continue;
        const int jb = ybase - fy;             // window row of k=0 output
        if (jb > 32 || jb < -3) continue;

        const float4 w = sw[n];
        const bool c0 = (i <= 31);             // P[.][i]   in patch
        const bool c1 = (i >= 1);              // P[.][i-1] in patch
        const float* Pn = Pb + (size_t)n * (C * PH * PW);

#pragma unroll
        for (int c = 0; c < C; c++) {
            const float* Pc = Pn + c * (PH * PW);
            // h[r] = x-filtered patch row rr = jb-1+r (zero outside patch)
            float h[5];
#pragma unroll
            for (int r = 0; r < 5; r++) {
                const int rr = jb - 1 + r;
                const bool rv = ((unsigned)rr < 32u);
                const float p0 = (rv & c0) ? __ldg(Pc + rr * PW + i)       : 0.0f;
                const float p1 = (rv & c1) ? __ldg(Pc + rr * PW + (i - 1)) : 0.0f;
                h[r] = w.x * p0 + w.y * p1;
            }
            // output row j = jb+k: v = wy0*h_at(j) + wy1*h_at(j-1)
            // (rows outside [0,31] already zero via load predicates)
#pragma unroll
            for (int k = 0; k < 4; k++)
                acc[k][c] += w.z * h[k + 1] + w.w * h[k];
        }
    }

    // coalesced stores: [b][c][y][x]
#pragma unroll
    for (int c = 0; c < C; c++) {
        float* oc = out + ((size_t)(b * C + c) * IMAGE_H) * IMAGE_W;
#pragma unroll
        for (int k = 0; k < 4; k++)
            oc[(size_t)(ybase + k) * IMAGE_W + x] = acc[k][c];
    }
}

extern "C" void kernel_launch(void* const* d_in, const int* in_sizes, int n_in,
                              void* d_out, int out_size)
{
    const float* brushes = (const float*)d_in[0];   // [16,64,2]
    const float* patches = (const float*)d_in[1];   // [16,64,3,32,32]
    float* out = (float*)d_out;                     // [16,3,256,256]

    dim3 grid(64, B);
    brush_fused_kernel<<<grid, 256>>>(brushes, patches, out);
}

// round 4
// speedup vs baseline: 1.6494x; 1.6494x over previous
#include <cuda_runtime.h>
#include <math.h>

#define IMAGE_W 256
#define IMAGE_H 256
#define EPS 1e-7f
#define SIGMA2 0.02f

#define B 16
#define N 64
#define C 3
#define PH 32
#define PW 32
#define TILE 32

// One block per (batch, 32x32 tile). 512 threads: thread (lx, g) owns pixel
// column x = tx0+lx, rows ybase = ty0 + 2g .. +1 (2 rows) x 3 channels.
// Survivor strokes found via ballot; taps read straight from global (L2-hot).
__global__ void __launch_bounds__(512) brush_fused_kernel(
    const float* __restrict__ brushes,   // [B, N, 2]
    const float* __restrict__ patches,   // [B, N, 3, 32, 32]
    float* __restrict__ out)             // [B, 3, 256, 256]
{
    const int b    = blockIdx.y;
    const int tile = blockIdx.x;           // 0..63
    const int tx0  = (tile & 7) * TILE;
    const int ty0  = (tile >> 3) * TILE;
    const int tid  = threadIdx.x;

    __shared__ int      sfx[N], sfy[N];
    __shared__ float4   sw[N];             // (wx0, wx1, wy0/64, wy1/64)
    __shared__ float    s_red[4][2];       // per-warp min/max partials
    __shared__ unsigned smask[2];          // survivor bitmask (strokes 0..31, 32..63)

    // ---- phase 1: load brush, butterfly min/max within each of 2 warps ----
    float bx = 0.0f, by = 0.0f;
    if (tid < N) {
        bx = brushes[(b * N + tid) * 2 + 0];
        by = brushes[(b * N + tid) * 2 + 1];
        float mnx = bx, mxx = bx, mny = by, mxy = by;
#pragma unroll
        for (int o = 16; o > 0; o >>= 1) {
            mnx = fminf(mnx, __shfl_xor_sync(0xffffffffu, mnx, o));
            mxx = fmaxf(mxx, __shfl_xor_sync(0xffffffffu, mxx, o));
            mny = fminf(mny, __shfl_xor_sync(0xffffffffu, mny, o));
            mxy = fmaxf(mxy, __shfl_xor_sync(0xffffffffu, mxy, o));
        }
        if ((tid & 31) == 0) {
            const int w = tid >> 5;
            s_red[0][w] = mnx; s_red[1][w] = mxx;
            s_red[2][w] = mny; s_red[3][w] = mxy;
        }
    }
    __syncthreads();

    // ---- phase 2: per-stroke params + ballot survivor mask ----
    if (tid < N) {
        const float mnx = fminf(s_red[0][0], s_red[0][1]);
        const float mxx = fmaxf(s_red[1][0], s_red[1][1]);
        const float mny = fminf(s_red[2][0], s_red[2][1]);
        const float mxy = fmaxf(s_red[3][0], s_red[3][1]);

        const float gx = (bx - mnx) / (mxx - mnx + EPS) * (float)IMAGE_W;
        const float gy = (by - mny) / (mxy - mny + EPS) * (float)IMAGE_H;

        const float axc = gx - 15.5f;          // ux(q) = gx + q - 15.5
        const float fx0f = floorf(axc);
        const float dx = axc - fx0f;
        const float ayc = gy - 15.4f;          // uy(p) = gy + p - 15.4
        const float fy0f = floorf(ayc);
        const float dy = ayc - fy0f;

        const float gx0 = __expf(-(dx * dx) / SIGMA2);
        const float gx1 = __expf(-((1.0f - dx) * (1.0f - dx)) / SIGMA2);
        const float wx0 = gx0 / (gx0 + gx1 + EPS);
        const float wx1 = gx1 / (gx0 + gx1 + EPS);

        const float gy0 = __expf(-(dy * dy) / SIGMA2);
        const float gy1 = __expf(-((1.0f - dy) * (1.0f - dy)) / SIGMA2);
        const float s  = 1.0f / 64.0f;         // fold /N into wy
        const float wy0 = gy0 / (gy0 + gy1 + EPS) * s;
        const float wy1 = gy1 / (gy0 + gy1 + EPS) * s;

        const int fx = (int)fx0f;
        const int fy = (int)fy0f;
        sfx[tid] = fx;
        sfy[tid] = fy;
        sw[tid]  = make_float4(wx0, wx1, wy0, wy1);

        // window [fx, fx+32] x [fy, fy+32] vs tile [tx0, tx0+31] x [ty0, ty0+31]
        const bool ov = !(fx > tx0 + 31 || fx + 32 < tx0 ||
                          fy > ty0 + 31 || fy + 32 < ty0);
        const unsigned m = __ballot_sync(0xffffffffu, ov);
        if ((tid & 31) == 0) smask[tid >> 5] = m;
    }
    __syncthreads();

    // ---- main: iterate only surviving strokes ----
    const int lx    = tid & 31;
    const int g     = tid >> 5;                // 0..15
    const int x     = tx0 + lx;
    const int ybase = ty0 + g * 2;             // rows ybase, ybase+1

    float acc[C][2];
#pragma unroll
    for (int c = 0; c < C; c++) { acc[c][0] = 0.0f; acc[c][1] = 0.0f; }

    const float* Pb = patches + (size_t)(b * N) * (C * PH * PW);

#pragma unroll
    for (int w = 0; w < 2; w++) {
        unsigned m = smask[w];
        while (m) {
            const int bit = __ffs(m) - 1;
            m &= m - 1;
            const int n = bit + w * 32;

            const int fx = sfx[n];
            const int fy = sfy[n];
            const int i  = x - fx;             // window col, valid 0..32
            const int jb = ybase - fy;         // window row of k=0 output
            if ((unsigned)i > 32u) continue;
            if (jb < -1 || jb > 32) continue;

            const float4 wt = sw[n];
            const bool c0 = (i <= 31);         // P[.][i]   in patch
            const bool c1 = (i >= 1);          // P[.][i-1] in patch
            const float* Pn = Pb + (size_t)n * (C * PH * PW) + i;

#pragma unroll
            for (int c = 0; c < C; c++) {
                const float* Pc = Pn + c * (PH * PW);
                float h[3];                    // x-filtered rows jb-1, jb, jb+1
#pragma unroll
                for (int r = 0; r < 3; r++) {
                    const int rr = jb - 1 + r;
                    const bool rv = ((unsigned)rr < 32u);
                    const float p0 = (rv & c0) ? __ldg(Pc + rr * PW)     : 0.0f;
                    const float p1 = (rv & c1) ? __ldg(Pc + rr * PW - 1) : 0.0f;
                    h[r] = wt.x * p0 + wt.y * p1;
                }
                acc[c][0] += wt.z * h[1] + wt.w * h[0];
                acc[c][1] += wt.z * h[2] + wt.w * h[1];
            }
        }
    }

    // ---- coalesced stores: [b][c][y][x] ----
#pragma unroll
    for (int c = 0; c < C; c++) {
        float* oc = out + ((size_t)(b * C + c) * IMAGE_H) * IMAGE_W;
        oc[(size_t)(ybase    ) * IMAGE_W + x] = acc[c][0];
        oc[(size_t)(ybase + 1) * IMAGE_W + x] = acc[c][1];
    }
}

extern "C" void kernel_launch(void* const* d_in, const int* in_sizes, int n_in,
                              void* d_out, int out_size)
{
    const float* brushes = (const float*)d_in[0];   // [16,64,2]
    const float* patches = (const float*)d_in[1];   // [16,64,3,32,32]
    float* out = (float*)d_out;                     // [16,3,256,256]

    dim3 grid(64, B);
    brush_fused_kernel<<<grid, 512>>>(brushes, patches, out);
}